// round 1
// baseline (speedup 1.0000x reference)
#include <cuda_runtime.h>

// Problem constants (fixed shapes from reference):
//   outputs1/2, input1/2 : [64,3,256,256] f32  -> NEL = 12,582,912 each
//   z1/z2                : [64,64,16,16]  f32  -> [64, 16384] flattened
#define BZ 64
#define DZ 16384
#define NEL 12582912
#define N4 (NEL / 4)

#define NCTR_BLOCKS 64          // contrastive blocks, each owns a 256-wide D slice
#define NMSE_BLOCKS 1184        // 148 SMs * 8
#define TOTAL_BLOCKS (NCTR_BLOCKS + NMSE_BLOCKS)

// Deterministic scratch (no atomics, every slot rewritten every launch)
__device__ float  g_crossp[NCTR_BLOCKS * 64 * 64];  // per-block partial cross[m][n]
__device__ float  g_sqp[NCTR_BLOCKS * 128];         // per-block partial sq: [b][tensor*64+row]
__device__ double g_msep[NMSE_BLOCKS];              // per-block MSE partial sums

__global__ __launch_bounds__(256)
void fused_kernel(const float* __restrict__ o1, const float* __restrict__ z1,
                  const float* __restrict__ o2, const float* __restrict__ z2,
                  const float* __restrict__ i1, const float* __restrict__ i2)
{
    const int tid = threadIdx.x;
    const int b   = blockIdx.x;

    if (b < NCTR_BLOCKS) {
        // ---------- contrastive cross-matrix partial: D slice [b*256, b*256+256) ----------
        // Shared tiles stored k-major: s[k][row], row padded to 68 (68*4 = 272 = 17*16,
        // so &s[k][4*t] stays 16B aligned for LDS.128 on the compute side).
        __shared__ __align__(16) float s1[32][68];
        __shared__ __align__(16) float s2[32][68];

        float acc[4][4];
#pragma unroll
        for (int i = 0; i < 4; ++i)
#pragma unroll
            for (int j = 0; j < 4; ++j) acc[i][j] = 0.0f;

        const int tx = tid & 15;   // n-tile coordinate
        const int ty = tid >> 4;   // m-tile coordinate
        const int c0 = b * 256;

        for (int t = 0; t < 8; ++t) {          // 8 k-tiles of 32
            const int ck = c0 + t * 32;
            __syncthreads();
            // load 64 rows x 32 k each tensor: 512 float4 per tensor, 2 per thread
#pragma unroll
            for (int i = 0; i < 2; ++i) {
                const int idx = tid + i * 256;      // 0..511
                const int r   = idx >> 3;           // row 0..63
                const int kk  = (idx & 7) * 4;      // k within tile
                float4 v1 = *(const float4*)(z1 + r * DZ + ck + kk);
                float4 v2 = *(const float4*)(z2 + r * DZ + ck + kk);
                s1[kk + 0][r] = v1.x; s1[kk + 1][r] = v1.y;
                s1[kk + 2][r] = v1.z; s1[kk + 3][r] = v1.w;
                s2[kk + 0][r] = v2.x; s2[kk + 1][r] = v2.y;
                s2[kk + 2][r] = v2.z; s2[kk + 3][r] = v2.w;
            }
            __syncthreads();
#pragma unroll
            for (int k = 0; k < 32; ++k) {
                const float4 av = *(const float4*)&s1[k][ty * 4];
                const float4 bv = *(const float4*)&s2[k][tx * 4];
                const float a[4] = {av.x, av.y, av.z, av.w};
                const float c[4] = {bv.x, bv.y, bv.z, bv.w};
#pragma unroll
                for (int i = 0; i < 4; ++i)
#pragma unroll
                    for (int j = 0; j < 4; ++j) acc[i][j] += a[i] * c[j];
            }
        }

        float* outp = g_crossp + b * 4096;
#pragma unroll
        for (int i = 0; i < 4; ++i)
#pragma unroll
            for (int j = 0; j < 4; ++j)
                outp[(ty * 4 + i) * 64 + (tx * 4 + j)] = acc[i][j];

        // ---------- per-row sum-of-squares partial over this slice ----------
        const int tensor = tid >> 7;          // 0 -> z1, 1 -> z2
        const int row    = (tid >> 1) & 63;
        const int half   = tid & 1;
        const float* zp  = tensor ? z2 : z1;
        const float4* zr = (const float4*)(zp + row * DZ + c0 + half * 128);
        float s = 0.0f;
#pragma unroll
        for (int c = 0; c < 32; ++c) {
            float4 v = zr[c];
            s += v.x * v.x + v.y * v.y + v.z * v.z + v.w * v.w;
        }
        s += __shfl_xor_sync(0xffffffffu, s, 1);   // combine the two halves (adjacent lanes)
        if (half == 0) g_sqp[b * 128 + tensor * 64 + row] = s;
    } else {
        // ---------- MSE: grid-stride float4 over both (output,input) pairs ----------
        const int mb = b - NCTR_BLOCKS;
        const float4* a1 = (const float4*)o1;
        const float4* c1 = (const float4*)i1;
        const float4* a2 = (const float4*)o2;
        const float4* c2 = (const float4*)i2;
        float sum = 0.0f;
        for (int idx = mb * 256 + tid; idx < N4; idx += NMSE_BLOCKS * 256) {
            float4 x = a1[idx], y = c1[idx];
            float dx = x.x - y.x, dy = x.y - y.y, dz = x.z - y.z, dw = x.w - y.w;
            sum += dx * dx + dy * dy + dz * dz + dw * dw;
            x = a2[idx]; y = c2[idx];
            dx = x.x - y.x; dy = x.y - y.y; dz = x.z - y.z; dw = x.w - y.w;
            sum += dx * dx + dy * dy + dz * dz + dw * dw;
        }
        __shared__ float red[8];
#pragma unroll
        for (int off = 16; off; off >>= 1) sum += __shfl_down_sync(0xffffffffu, sum, off);
        if ((tid & 31) == 0) red[tid >> 5] = sum;
        __syncthreads();
        if (tid < 32) {
            float v = (tid < 8) ? red[tid] : 0.0f;
#pragma unroll
            for (int off = 4; off; off >>= 1) v += __shfl_down_sync(0xffffffffu, v, off);
            if (tid == 0) g_msep[mb] = (double)v;
        }
    }
}

__global__ __launch_bounds__(256)
void finalize_kernel(float* __restrict__ out)
{
    const int tid = threadIdx.x;
    __shared__ float  ssq[128];
    __shared__ double rd[256];
    __shared__ double res[3];

    // reduce sum-of-squares partials: ssq[0..63]=sq1 rows, ssq[64..127]=sq2 rows
    if (tid < 128) {
        float s = 0.0f;
        for (int bb = 0; bb < NCTR_BLOCKS; ++bb) s += g_sqp[bb * 128 + tid];
        ssq[tid] = s;
    }
    // reduce MSE partials
    double msum = 0.0;
    for (int i = tid; i < NMSE_BLOCKS; i += 256) msum += g_msep[i];
    __syncthreads();

    // reduce cross partials and apply margins
    double lp = 0.0, ln = 0.0;
    for (int idx = tid; idx < 4096; idx += 256) {
        float cr = 0.0f;
        for (int bb = 0; bb < NCTR_BLOCKS; ++bb) cr += g_crossp[bb * 4096 + idx];
        const int m = idx >> 6, n = idx & 63;
        const double dmn = ((double)ssq[m] + (double)ssq[64 + n] - 2.0 * (double)cr)
                           * (1.0 / (double)DZ);
        if (m == n) {
            if (dmn > 0.01) lp += dmn - 0.01;
        } else if (dmn < 0.4) {
            ln += 0.4 - dmn;
        }
    }

    // three block reductions (msum, lp, ln)
    double vals[3] = {msum, lp, ln};
    for (int q = 0; q < 3; ++q) {
        rd[tid] = vals[q];
        __syncthreads();
        for (int s = 128; s; s >>= 1) {
            if (tid < s) rd[tid] += rd[tid + s];
            __syncthreads();
        }
        if (tid == 0) res[q] = rd[0];
        __syncthreads();
    }

    if (tid == 0) {
        const double recon = res[0] / (double)NEL;                 // mean1 + mean2 combined
        const double lossP = 1.5 * (res[1] / (double)BZ);
        const double lossN = 0.5 * (res[2] / (double)(BZ * (BZ - 1)));
        out[0] = (float)(recon + lossP + lossN);
    }
}

extern "C" void kernel_launch(void* const* d_in, const int* in_sizes, int n_in,
                              void* d_out, int out_size)
{
    const float* o1 = (const float*)d_in[0];
    const float* z1 = (const float*)d_in[1];
    const float* o2 = (const float*)d_in[2];
    const float* z2 = (const float*)d_in[3];
    const float* i1 = (const float*)d_in[4];
    const float* i2 = (const float*)d_in[5];

    fused_kernel<<<TOTAL_BLOCKS, 256>>>(o1, z1, o2, z2, i1, i2);
    finalize_kernel<<<1, 256>>>((float*)d_out);
}

// round 2
// speedup vs baseline: 1.2481x; 1.2481x over previous
#include <cuda_runtime.h>

// Problem constants (fixed shapes from reference):
//   outputs1/2, input1/2 : [64,3,256,256] f32  -> NEL = 12,582,912 each
//   z1/z2                : [64,64,16,16]  f32  -> [64, 16384] flattened
#define BZ 64
#define DZ 16384
#define NEL 12582912
#define N4 (NEL / 4)

#define NCTR_BLOCKS 64          // contrastive blocks, each owns a 256-wide D slice
#define NMSE_BLOCKS 1184        // 148 SMs * 8
#define TOTAL_BLOCKS (NCTR_BLOCKS + NMSE_BLOCKS)

// Deterministic scratch (no atomics, every slot rewritten every launch)
__device__ float  g_crossp[NCTR_BLOCKS * 64 * 64];  // per-block partial cross[m][n]
__device__ float  g_sqp[NCTR_BLOCKS * 128];         // per-block partial sq: [b][tensor*64+row]
__device__ double g_msep[NMSE_BLOCKS];              // per-block MSE partial sums

__global__ __launch_bounds__(256)
void fused_kernel(const float* __restrict__ o1, const float* __restrict__ z1,
                  const float* __restrict__ o2, const float* __restrict__ z2,
                  const float* __restrict__ i1, const float* __restrict__ i2)
{
    const int tid = threadIdx.x;
    const int b   = blockIdx.x;

    if (b < NCTR_BLOCKS) {
        // ---------- contrastive cross-matrix partial: D slice [b*256, b*256+256) ----------
        // Shared tiles stored k-major: s[k][row], row padded to 68 (68*4 = 272 = 17*16,
        // so &s[k][4*t] stays 16B aligned for LDS.128 on the compute side).
        __shared__ __align__(16) float s1[32][68];
        __shared__ __align__(16) float s2[32][68];

        float acc[4][4];
#pragma unroll
        for (int i = 0; i < 4; ++i)
#pragma unroll
            for (int j = 0; j < 4; ++j) acc[i][j] = 0.0f;

        const int tx = tid & 15;   // n-tile coordinate
        const int ty = tid >> 4;   // m-tile coordinate
        const int c0 = b * 256;

        for (int t = 0; t < 8; ++t) {          // 8 k-tiles of 32
            const int ck = c0 + t * 32;
            __syncthreads();
            // load 64 rows x 32 k each tensor: 512 float4 per tensor, 2 per thread
#pragma unroll
            for (int i = 0; i < 2; ++i) {
                const int idx = tid + i * 256;      // 0..511
                const int r   = idx >> 3;           // row 0..63
                const int kk  = (idx & 7) * 4;      // k within tile
                float4 v1 = *(const float4*)(z1 + r * DZ + ck + kk);
                float4 v2 = *(const float4*)(z2 + r * DZ + ck + kk);
                s1[kk + 0][r] = v1.x; s1[kk + 1][r] = v1.y;
                s1[kk + 2][r] = v1.z; s1[kk + 3][r] = v1.w;
                s2[kk + 0][r] = v2.x; s2[kk + 1][r] = v2.y;
                s2[kk + 2][r] = v2.z; s2[kk + 3][r] = v2.w;
            }
            __syncthreads();
#pragma unroll
            for (int k = 0; k < 32; ++k) {
                const float4 av = *(const float4*)&s1[k][ty * 4];
                const float4 bv = *(const float4*)&s2[k][tx * 4];
                const float a[4] = {av.x, av.y, av.z, av.w};
                const float c[4] = {bv.x, bv.y, bv.z, bv.w};
#pragma unroll
                for (int i = 0; i < 4; ++i)
#pragma unroll
                    for (int j = 0; j < 4; ++j) acc[i][j] += a[i] * c[j];
            }
        }

        float* outp = g_crossp + b * 4096;
#pragma unroll
        for (int i = 0; i < 4; ++i)
#pragma unroll
            for (int j = 0; j < 4; ++j)
                outp[(ty * 4 + i) * 64 + (tx * 4 + j)] = acc[i][j];

        // ---------- per-row sum-of-squares partial over this slice ----------
        const int tensor = tid >> 7;          // 0 -> z1, 1 -> z2
        const int row    = (tid >> 1) & 63;
        const int half   = tid & 1;
        const float* zp  = tensor ? z2 : z1;
        const float4* zr = (const float4*)(zp + row * DZ + c0 + half * 128);
        float s = 0.0f;
#pragma unroll
        for (int c = 0; c < 32; ++c) {
            float4 v = zr[c];
            s += v.x * v.x + v.y * v.y + v.z * v.z + v.w * v.w;
        }
        s += __shfl_xor_sync(0xffffffffu, s, 1);   // combine the two halves (adjacent lanes)
        if (half == 0) g_sqp[b * 128 + tensor * 64 + row] = s;
    } else {
        // ---------- MSE: grid-stride float4 over both (output,input) pairs ----------
        const int mb = b - NCTR_BLOCKS;
        const float4* a1 = (const float4*)o1;
        const float4* c1 = (const float4*)i1;
        const float4* a2 = (const float4*)o2;
        const float4* c2 = (const float4*)i2;
        float sum = 0.0f;
        for (int idx = mb * 256 + tid; idx < N4; idx += NMSE_BLOCKS * 256) {
            float4 x = a1[idx], y = c1[idx];
            float dx = x.x - y.x, dy = x.y - y.y, dz = x.z - y.z, dw = x.w - y.w;
            sum += dx * dx + dy * dy + dz * dz + dw * dw;
            x = a2[idx]; y = c2[idx];
            dx = x.x - y.x; dy = x.y - y.y; dz = x.z - y.z; dw = x.w - y.w;
            sum += dx * dx + dy * dy + dz * dz + dw * dw;
        }
        __shared__ float red[8];
#pragma unroll
        for (int off = 16; off; off >>= 1) sum += __shfl_down_sync(0xffffffffu, sum, off);
        if ((tid & 31) == 0) red[tid >> 5] = sum;
        __syncthreads();
        if (tid < 32) {
            float v = (tid < 8) ? red[tid] : 0.0f;
#pragma unroll
            for (int off = 4; off; off >>= 1) v += __shfl_down_sync(0xffffffffu, v, off);
            if (tid == 0) g_msep[mb] = (double)v;
        }
    }
}

__device__ __forceinline__ double warp_red_d(double v)
{
#pragma unroll
    for (int o = 16; o; o >>= 1) v += __shfl_down_sync(0xffffffffu, v, o);
    return v;
}

// 1024 threads: each thread owns 4 contiguous (m,n) entries of the 64x64 cross
// matrix -> the 64-way partial reduction is 64 independent LDG.128 per thread.
__global__ __launch_bounds__(1024)
void finalize_kernel(float* __restrict__ out)
{
    const int tid = threadIdx.x;
    __shared__ float  ssq[128];
    __shared__ double sred[3][32];

    // reduce sum-of-squares partials: ssq[0..63]=sq1 rows, ssq[64..127]=sq2 rows
    if (tid < 128) {
        float s = 0.0f;
#pragma unroll 8
        for (int bb = 0; bb < NCTR_BLOCKS; ++bb) s += g_sqp[bb * 128 + tid];
        ssq[tid] = s;
    }

    // reduce MSE partials (1184 doubles over 1024 threads)
    double msum = 0.0;
    for (int i = tid; i < NMSE_BLOCKS; i += 1024) msum += g_msep[i];
    __syncthreads();

    // reduce cross partials: thread tid owns entries [4*tid, 4*tid+4) of the
    // flattened 64x64 matrix. All 64 loads independent, vectorized LDG.128.
    const float4* cp = (const float4*)g_crossp;
    float4 cr = make_float4(0.f, 0.f, 0.f, 0.f);
#pragma unroll 16
    for (int bb = 0; bb < NCTR_BLOCKS; ++bb) {
        const float4 v = cp[bb * 1024 + tid];
        cr.x += v.x; cr.y += v.y; cr.z += v.z; cr.w += v.w;
    }

    const int m  = tid >> 4;
    const int n0 = (tid & 15) * 4;
    const float crr[4] = {cr.x, cr.y, cr.z, cr.w};
    double lp = 0.0, ln = 0.0;
#pragma unroll
    for (int j = 0; j < 4; ++j) {
        const int n = n0 + j;
        const double d = ((double)ssq[m] + (double)ssq[64 + n] - 2.0 * (double)crr[j])
                         * (1.0 / (double)DZ);
        if (m == n) {
            if (d > 0.01) lp += d - 0.01;
        } else if (d < 0.4) {
            ln += 0.4 - d;
        }
    }

    // three-scalar block reduction via warp shuffles
    double vals[3] = {msum, lp, ln};
    const int lane = tid & 31, w = tid >> 5;
#pragma unroll
    for (int q = 0; q < 3; ++q) {
        const double r = warp_red_d(vals[q]);
        if (lane == 0) sred[q][w] = r;
    }
    __syncthreads();
    if (tid < 32) {
        double r0 = warp_red_d(sred[0][tid]);
        double r1 = warp_red_d(sred[1][tid]);
        double r2 = warp_red_d(sred[2][tid]);
        if (tid == 0) {
            const double recon = r0 / (double)NEL;                  // mean1 + mean2 combined
            const double lossP = 1.5 * (r1 / (double)BZ);
            const double lossN = 0.5 * (r2 / (double)(BZ * (BZ - 1)));
            out[0] = (float)(recon + lossP + lossN);
        }
    }
}

extern "C" void kernel_launch(void* const* d_in, const int* in_sizes, int n_in,
                              void* d_out, int out_size)
{
    const float* o1 = (const float*)d_in[0];
    const float* z1 = (const float*)d_in[1];
    const float* o2 = (const float*)d_in[2];
    const float* z2 = (const float*)d_in[3];
    const float* i1 = (const float*)d_in[4];
    const float* i2 = (const float*)d_in[5];

    fused_kernel<<<TOTAL_BLOCKS, 256>>>(o1, z1, o2, z2, i1, i2);
    finalize_kernel<<<1, 1024>>>((float*)d_out);
}

// round 3
// speedup vs baseline: 1.3768x; 1.1032x over previous
#include <cuda_runtime.h>

// Problem constants (fixed shapes from reference):
//   outputs1/2, input1/2 : [64,3,256,256] f32  -> NEL = 12,582,912 each
//   z1/z2                : [64,64,16,16]  f32  -> [64, 16384] flattened
#define BZ 64
#define DZ 16384
#define NEL 12582912
#define N4 (NEL / 4)

#define NCTR_BLOCKS 64          // contrastive blocks, each owns a 256-wide D slice
#define NMSE_BLOCKS 1120        // 64 + 1120 = 1184 = 8 blocks * 148 SMs -> exactly one wave
#define TOTAL_BLOCKS (NCTR_BLOCKS + NMSE_BLOCKS)

// Deterministic scratch (no atomics, every slot rewritten every launch)
__device__ float  g_crossp[NCTR_BLOCKS * 64 * 64];  // per-block partial cross[m][n]
__device__ float  g_sqp[NCTR_BLOCKS * 128];         // per-block partial sq: [b][tensor*64+row]
__device__ double g_msep[NMSE_BLOCKS];              // per-block MSE partial sums
__device__ float  g_cross[64 * 64];                 // fully reduced cross matrix
__device__ float  g_sq[128];                        // fully reduced row sums of squares

__global__ __launch_bounds__(256)
void fused_kernel(const float* __restrict__ o1, const float* __restrict__ z1,
                  const float* __restrict__ o2, const float* __restrict__ z2,
                  const float* __restrict__ i1, const float* __restrict__ i2)
{
    const int tid = threadIdx.x;
    const int b   = blockIdx.x;

    if (b < NCTR_BLOCKS) {
        // ---------- contrastive cross-matrix partial: D slice [b*256, b*256+256) ----------
        // Shared tiles stored k-major: s[k][row], row padded to 68 (68*4 = 272 = 17*16,
        // so &s[k][4*t] stays 16B aligned for LDS.128 on the compute side).
        __shared__ __align__(16) float s1[32][68];
        __shared__ __align__(16) float s2[32][68];

        float acc[4][4];
#pragma unroll
        for (int i = 0; i < 4; ++i)
#pragma unroll
            for (int j = 0; j < 4; ++j) acc[i][j] = 0.0f;

        const int tx = tid & 15;   // n-tile coordinate
        const int ty = tid >> 4;   // m-tile coordinate
        const int c0 = b * 256;

        for (int t = 0; t < 8; ++t) {          // 8 k-tiles of 32
            const int ck = c0 + t * 32;
            __syncthreads();
            // load 64 rows x 32 k each tensor: 512 float4 per tensor, 2 per thread
#pragma unroll
            for (int i = 0; i < 2; ++i) {
                const int idx = tid + i * 256;      // 0..511
                const int r   = idx >> 3;           // row 0..63
                const int kk  = (idx & 7) * 4;      // k within tile
                float4 v1 = *(const float4*)(z1 + r * DZ + ck + kk);
                float4 v2 = *(const float4*)(z2 + r * DZ + ck + kk);
                s1[kk + 0][r] = v1.x; s1[kk + 1][r] = v1.y;
                s1[kk + 2][r] = v1.z; s1[kk + 3][r] = v1.w;
                s2[kk + 0][r] = v2.x; s2[kk + 1][r] = v2.y;
                s2[kk + 2][r] = v2.z; s2[kk + 3][r] = v2.w;
            }
            __syncthreads();
#pragma unroll
            for (int k = 0; k < 32; ++k) {
                const float4 av = *(const float4*)&s1[k][ty * 4];
                const float4 bv = *(const float4*)&s2[k][tx * 4];
                const float a[4] = {av.x, av.y, av.z, av.w};
                const float c[4] = {bv.x, bv.y, bv.z, bv.w};
#pragma unroll
                for (int i = 0; i < 4; ++i)
#pragma unroll
                    for (int j = 0; j < 4; ++j) acc[i][j] += a[i] * c[j];
            }
        }

        float* outp = g_crossp + b * 4096;
#pragma unroll
        for (int i = 0; i < 4; ++i)
#pragma unroll
            for (int j = 0; j < 4; ++j)
                outp[(ty * 4 + i) * 64 + (tx * 4 + j)] = acc[i][j];

        // ---------- per-row sum-of-squares partial over this slice ----------
        const int tensor = tid >> 7;          // 0 -> z1, 1 -> z2
        const int row    = (tid >> 1) & 63;
        const int half   = tid & 1;
        const float* zp  = tensor ? z2 : z1;
        const float4* zr = (const float4*)(zp + row * DZ + c0 + half * 128);
        float s = 0.0f;
#pragma unroll
        for (int c = 0; c < 32; ++c) {
            float4 v = zr[c];
            s += v.x * v.x + v.y * v.y + v.z * v.z + v.w * v.w;
        }
        s += __shfl_xor_sync(0xffffffffu, s, 1);   // combine the two halves (adjacent lanes)
        if (half == 0) g_sqp[b * 128 + tensor * 64 + row] = s;
    } else {
        // ---------- MSE: grid-stride float4 over both (output,input) pairs ----------
        const int mb = b - NCTR_BLOCKS;
        const float4* a1 = (const float4*)o1;
        const float4* c1 = (const float4*)i1;
        const float4* a2 = (const float4*)o2;
        const float4* c2 = (const float4*)i2;
        float sum = 0.0f;
        for (int idx = mb * 256 + tid; idx < N4; idx += NMSE_BLOCKS * 256) {
            float4 x = __ldcs(a1 + idx), y = __ldcs(c1 + idx);
            float dx = x.x - y.x, dy = x.y - y.y, dz = x.z - y.z, dw = x.w - y.w;
            sum += dx * dx + dy * dy + dz * dz + dw * dw;
            x = __ldcs(a2 + idx); y = __ldcs(c2 + idx);
            dx = x.x - y.x; dy = x.y - y.y; dz = x.z - y.z; dw = x.w - y.w;
            sum += dx * dx + dy * dy + dz * dz + dw * dw;
        }
        __shared__ float red[8];
#pragma unroll
        for (int off = 16; off; off >>= 1) sum += __shfl_down_sync(0xffffffffu, sum, off);
        if ((tid & 31) == 0) red[tid >> 5] = sum;
        __syncthreads();
        if (tid < 32) {
            float v = (tid < 8) ? red[tid] : 0.0f;
#pragma unroll
            for (int off = 4; off; off >>= 1) v += __shfl_down_sync(0xffffffffu, v, off);
            if (tid == 0) g_msep[mb] = (double)v;
        }
    }
}

// Multi-block reduction of the 64-deep partials. Blocks 0..63 each own one
// m-row of the cross matrix (64 entries x 64 partials = 16KB); block 64
// reduces the sum-of-squares partials.
__global__ __launch_bounds__(256)
void reduce2_kernel()
{
    const int tid = threadIdx.x;
    if (blockIdx.x < 64) {
        const int m = blockIdx.x;
        const int n = tid & 63;       // output column
        const int q = tid >> 6;       // partial group 0..3 (16 partials each)
        float s = 0.0f;
#pragma unroll
        for (int j = 0; j < 16; ++j)
            s += g_crossp[(q * 16 + j) * 4096 + m * 64 + n];
        __shared__ float sm[4][64];
        sm[q][n] = s;
        __syncthreads();
        if (tid < 64)
            g_cross[m * 64 + tid] = sm[0][tid] + sm[1][tid] + sm[2][tid] + sm[3][tid];
    } else {
        // block 64: reduce g_sqp [64 partials][128 entries]
        const int i = tid >> 1;       // entry 0..127
        const int h = tid & 1;        // half of partials
        float s = 0.0f;
#pragma unroll
        for (int j = 0; j < 32; ++j)
            s += g_sqp[(h * 32 + j) * 128 + i];
        s += __shfl_xor_sync(0xffffffffu, s, 1);
        if (h == 0) g_sq[i] = s;
    }
}

__device__ __forceinline__ double warp_red_d(double v)
{
#pragma unroll
    for (int o = 16; o; o >>= 1) v += __shfl_down_sync(0xffffffffu, v, o);
    return v;
}

__global__ __launch_bounds__(1024)
void finalize_kernel(float* __restrict__ out)
{
    const int tid = threadIdx.x;
    __shared__ float  ssq[128];
    __shared__ double sred[3][32];

    if (tid < 128) ssq[tid] = g_sq[tid];

    // reduce MSE partials (1120 doubles over 1024 threads)
    double msum = 0.0;
    for (int i = tid; i < NMSE_BLOCKS; i += 1024) msum += g_msep[i];
    __syncthreads();

    // thread tid owns entries [4*tid, 4*tid+4) of the reduced 64x64 matrix
    const float4 cr = *((const float4*)g_cross + tid);
    const int m  = tid >> 4;
    const int n0 = (tid & 15) * 4;
    const float crr[4] = {cr.x, cr.y, cr.z, cr.w};
    double lp = 0.0, ln = 0.0;
#pragma unroll
    for (int j = 0; j < 4; ++j) {
        const int n = n0 + j;
        const double d = ((double)ssq[m] + (double)ssq[64 + n] - 2.0 * (double)crr[j])
                         * (1.0 / (double)DZ);
        if (m == n) {
            if (d > 0.01) lp += d - 0.01;
        } else if (d < 0.4) {
            ln += 0.4 - d;
        }
    }

    // three-scalar block reduction via warp shuffles
    double vals[3] = {msum, lp, ln};
    const int lane = tid & 31, w = tid >> 5;
#pragma unroll
    for (int q = 0; q < 3; ++q) {
        const double r = warp_red_d(vals[q]);
        if (lane == 0) sred[q][w] = r;
    }
    __syncthreads();
    if (tid < 32) {
        double r0 = warp_red_d(sred[0][tid]);
        double r1 = warp_red_d(sred[1][tid]);
        double r2 = warp_red_d(sred[2][tid]);
        if (tid == 0) {
            const double recon = r0 / (double)NEL;                  // mean1 + mean2 combined
            const double lossP = 1.5 * (r1 / (double)BZ);
            const double lossN = 0.5 * (r2 / (double)(BZ * (BZ - 1)));
            out[0] = (float)(recon + lossP + lossN);
        }
    }
}

extern "C" void kernel_launch(void* const* d_in, const int* in_sizes, int n_in,
                              void* d_out, int out_size)
{
    const float* o1 = (const float*)d_in[0];
    const float* z1 = (const float*)d_in[1];
    const float* o2 = (const float*)d_in[2];
    const float* z2 = (const float*)d_in[3];
    const float* i1 = (const float*)d_in[4];
    const float* i2 = (const float*)d_in[5];

    fused_kernel<<<TOTAL_BLOCKS, 256>>>(o1, z1, o2, z2, i1, i2);
    reduce2_kernel<<<65, 256>>>();
    finalize_kernel<<<1, 1024>>>((float*)d_out);
}

// round 4
// speedup vs baseline: 1.9739x; 1.4337x over previous
#include <cuda_runtime.h>

// Problem constants (fixed shapes from reference):
//   outputs1/2, input1/2 : [64,3,256,256] f32  -> NEL = 12,582,912 each
//   z1/z2                : [64,64,16,16]  f32  -> [64, 16384] flattened
#define BZ 64
#define DZ 16384
#define NEL 12582912
#define N4 (NEL / 4)

#define NCTR_BLOCKS 64          // contrastive blocks, each owns a 256-wide D slice
#define NMSE_BLOCKS 528         // 64 + 528 = 592 = 4 CTAs/SM * 148 SMs -> exactly ONE wave (56 regs)
#define TOTAL_BLOCKS (NCTR_BLOCKS + NMSE_BLOCKS)

// Deterministic scratch (no atomics, every slot rewritten every launch)
__device__ float  g_crossp[NCTR_BLOCKS * 64 * 64];  // per-block partial cross[m][n]
__device__ float  g_sq[128];                        // COMPLETE row sums of squares (z1: 0..63, z2: 64..127)
__device__ double g_msep[NMSE_BLOCKS];              // per-block MSE partial sums
__device__ double g_row_lp[64];                     // per-row positive-margin term
__device__ double g_row_ln[64];                     // per-row negative-margin sum

__global__ __launch_bounds__(256)
void fused_kernel(const float* __restrict__ o1, const float* __restrict__ z1,
                  const float* __restrict__ o2, const float* __restrict__ z2,
                  const float* __restrict__ i1, const float* __restrict__ i2)
{
    const int tid = threadIdx.x;
    const int b   = blockIdx.x;

    if (b < NCTR_BLOCKS) {
        // ---------- contrastive cross-matrix partial: D slice [b*256, b*256+256) ----------
        // Shared tiles stored k-major: s[k][row], row padded to 68 (68*4 = 272 = 17*16,
        // so &s[k][4*t] stays 16B aligned for LDS.128 on the compute side).
        __shared__ __align__(16) float s1[32][68];
        __shared__ __align__(16) float s2[32][68];

        float acc[4][4];
#pragma unroll
        for (int i = 0; i < 4; ++i)
#pragma unroll
            for (int j = 0; j < 4; ++j) acc[i][j] = 0.0f;

        const int tx = tid & 15;   // n-tile coordinate
        const int ty = tid >> 4;   // m-tile coordinate
        const int c0 = b * 256;

        for (int t = 0; t < 8; ++t) {          // 8 k-tiles of 32
            const int ck = c0 + t * 32;
            __syncthreads();
            // load 64 rows x 32 k each tensor: 512 float4 per tensor, 2 per thread
#pragma unroll
            for (int i = 0; i < 2; ++i) {
                const int idx = tid + i * 256;      // 0..511
                const int r   = idx >> 3;           // row 0..63
                const int kk  = (idx & 7) * 4;      // k within tile
                float4 v1 = *(const float4*)(z1 + r * DZ + ck + kk);
                float4 v2 = *(const float4*)(z2 + r * DZ + ck + kk);
                s1[kk + 0][r] = v1.x; s1[kk + 1][r] = v1.y;
                s1[kk + 2][r] = v1.z; s1[kk + 3][r] = v1.w;
                s2[kk + 0][r] = v2.x; s2[kk + 1][r] = v2.y;
                s2[kk + 2][r] = v2.z; s2[kk + 3][r] = v2.w;
            }
            __syncthreads();
#pragma unroll
            for (int k = 0; k < 32; ++k) {
                const float4 av = *(const float4*)&s1[k][ty * 4];
                const float4 bv = *(const float4*)&s2[k][tx * 4];
                const float a[4] = {av.x, av.y, av.z, av.w};
                const float c[4] = {bv.x, bv.y, bv.z, bv.w};
#pragma unroll
                for (int i = 0; i < 4; ++i)
#pragma unroll
                    for (int j = 0; j < 4; ++j) acc[i][j] += a[i] * c[j];
            }
        }

        float* outp = g_crossp + b * 4096;
#pragma unroll
        for (int i = 0; i < 4; ++i)
#pragma unroll
            for (int j = 0; j < 4; ++j)
                outp[(ty * 4 + i) * 64 + (tx * 4 + j)] = acc[i][j];

        // ---------- COMPLETE sum of squares for row b of z1 (tids 0-127) / z2 (tids 128-255) ----------
        {
            const int g    = tid >> 7;          // 0 -> z1, 1 -> z2
            const int lt   = tid & 127;
            const float* zp = g ? z2 : z1;
            const float4* zr = (const float4*)(zp + b * DZ);
            float s = 0.0f;
#pragma unroll 8
            for (int i = lt; i < 4096; i += 128) {
                const float4 v = zr[i];
                s += v.x * v.x + v.y * v.y + v.z * v.z + v.w * v.w;
            }
#pragma unroll
            for (int o = 16; o; o >>= 1) s += __shfl_down_sync(0xffffffffu, s, o);
            __shared__ float sqred[2][4];
            if ((lt & 31) == 0) sqred[g][lt >> 5] = s;
            __syncthreads();
            if (lt == 0)
                g_sq[g * 64 + b] = sqred[g][0] + sqred[g][1] + sqred[g][2] + sqred[g][3];
        }
    } else {
        // ---------- MSE: grid-stride float4 over both (output,input) pairs ----------
        const int mb = b - NCTR_BLOCKS;
        const float4* a1 = (const float4*)o1;
        const float4* c1 = (const float4*)i1;
        const float4* a2 = (const float4*)o2;
        const float4* c2 = (const float4*)i2;
        float sum = 0.0f;
        for (int idx = mb * 256 + tid; idx < N4; idx += NMSE_BLOCKS * 256) {
            float4 x = __ldcs(a1 + idx), y = __ldcs(c1 + idx);
            float dx = x.x - y.x, dy = x.y - y.y, dz = x.z - y.z, dw = x.w - y.w;
            sum += dx * dx + dy * dy + dz * dz + dw * dw;
            x = __ldcs(a2 + idx); y = __ldcs(c2 + idx);
            dx = x.x - y.x; dy = x.y - y.y; dz = x.z - y.z; dw = x.w - y.w;
            sum += dx * dx + dy * dy + dz * dz + dw * dw;
        }
        __shared__ float red[8];
#pragma unroll
        for (int off = 16; off; off >>= 1) sum += __shfl_down_sync(0xffffffffu, sum, off);
        if ((tid & 31) == 0) red[tid >> 5] = sum;
        __syncthreads();
        if (tid < 32) {
            float v = (tid < 8) ? red[tid] : 0.0f;
#pragma unroll
            for (int off = 4; off; off >>= 1) v += __shfl_down_sync(0xffffffffu, v, off);
            if (tid == 0) g_msep[mb] = (double)v;
        }
    }
}

// Block m: reduce cross row m over the 64 partials, then apply margins for row m.
__global__ __launch_bounds__(256)
void rowreduce_kernel()
{
    const int tid = threadIdx.x;
    const int m   = blockIdx.x;
    const int n   = tid & 63;       // output column
    const int q   = tid >> 6;       // partial group 0..3 (16 partials each)

    float s = 0.0f;
#pragma unroll
    for (int j = 0; j < 16; ++j)
        s += g_crossp[(q * 16 + j) * 4096 + m * 64 + n];

    __shared__ float sm[4][64];
    __shared__ double dred[2];
    sm[q][n] = s;
    __syncthreads();

    if (tid < 64) {
        const float cr = sm[0][tid] + sm[1][tid] + sm[2][tid] + sm[3][tid];
        const double d = ((double)g_sq[m] + (double)g_sq[64 + tid] - 2.0 * (double)cr)
                         * (1.0 / (double)DZ);
        double lp = 0.0, ln = 0.0;
        if (m == tid) {
            if (d > 0.01) lp = d - 0.01;
        } else if (d < 0.4) {
            ln = 0.4 - d;
        }
        // reduce ln over 64 threads (2 warps); lp is nonzero on exactly one thread
#pragma unroll
        for (int o = 16; o; o >>= 1) {
            lp += __shfl_down_sync(0xffffffffu, lp, o);
            ln += __shfl_down_sync(0xffffffffu, ln, o);
        }
        if ((tid & 31) == 0) dred[tid >> 5] = ln + lp;   // lp folded in (only one warp has it)
        __syncthreads();
        if (tid == 0) {
            // separate lp exactly: recompute diagonal term directly (cheap, deterministic)
            const double dd = ((double)g_sq[m] + (double)g_sq[64 + m] - 2.0 * (double)(sm[0][m] + sm[1][m] + sm[2][m] + sm[3][m]))
                              * (1.0 / (double)DZ);
            const double lpv = (dd > 0.01) ? (dd - 0.01) : 0.0;
            g_row_lp[m] = lpv;
            g_row_ln[m] = dred[0] + dred[1] - lpv;
        }
    }
}

__device__ __forceinline__ double warp_red_d(double v)
{
#pragma unroll
    for (int o = 16; o; o >>= 1) v += __shfl_down_sync(0xffffffffu, v, o);
    return v;
}

__global__ __launch_bounds__(256)
void finalize_kernel(float* __restrict__ out)
{
    const int tid = threadIdx.x;
    __shared__ double sred[3][8];

    double msum = 0.0;
#pragma unroll
    for (int i = tid; i < NMSE_BLOCKS; i += 256) msum += g_msep[i];

    double lp = 0.0, ln = 0.0;
    if (tid < 64) { lp = g_row_lp[tid]; ln = g_row_ln[tid]; }

    const int lane = tid & 31, w = tid >> 5;
    const double r0 = warp_red_d(msum);
    const double r1 = warp_red_d(lp);
    const double r2 = warp_red_d(ln);
    if (lane == 0) { sred[0][w] = r0; sred[1][w] = r1; sred[2][w] = r2; }
    __syncthreads();
    if (tid == 0) {
        double t0 = 0.0, t1 = 0.0, t2 = 0.0;
#pragma unroll
        for (int i = 0; i < 8; ++i) { t0 += sred[0][i]; t1 += sred[1][i]; t2 += sred[2][i]; }
        const double recon = t0 / (double)NEL;                  // mean1 + mean2 combined
        const double lossP = 1.5 * (t1 / (double)BZ);
        const double lossN = 0.5 * (t2 / (double)(BZ * (BZ - 1)));
        out[0] = (float)(recon + lossP + lossN);
    }
}

extern "C" void kernel_launch(void* const* d_in, const int* in_sizes, int n_in,
                              void* d_out, int out_size)
{
    const float* o1 = (const float*)d_in[0];
    const float* z1 = (const float*)d_in[1];
    const float* o2 = (const float*)d_in[2];
    const float* z2 = (const float*)d_in[3];
    const float* i1 = (const float*)d_in[4];
    const float* i2 = (const float*)d_in[5];

    fused_kernel<<<TOTAL_BLOCKS, 256>>>(o1, z1, o2, z2, i1, i2);
    rowreduce_kernel<<<64, 256>>>();
    finalize_kernel<<<1, 256>>>((float*)d_out);
}

// round 5
// speedup vs baseline: 2.0094x; 1.0179x over previous
#include <cuda_runtime.h>

// Problem constants (fixed shapes from reference):
//   outputs1/2, input1/2 : [64,3,256,256] f32  -> NEL = 12,582,912 each
//   z1/z2                : [64,64,16,16]  f32  -> [64, 16384] flattened
#define BZ 64
#define DZ 16384
#define NEL 12582912
#define N4 (NEL / 4)

#define NCTR_BLOCKS 64          // contrastive blocks, each owns a 256-wide D slice
#define NMSE_BLOCKS 512         // each owns a contiguous 6144-float4 chunk -> exactly 24 iters/thread
#define MSE_ITERS 24            // 512 * 256 * 24 == N4
#define TOTAL_BLOCKS (NCTR_BLOCKS + NMSE_BLOCKS)   // 576 <= 592 = one wave at 4 CTAs/SM

// Deterministic scratch (no atomics, every slot rewritten every launch)
__device__ float  g_crossp[NCTR_BLOCKS * 64 * 64];  // per-block partial cross[m][n]
__device__ float  g_sq[128];                        // COMPLETE row sums of squares (z1: 0..63, z2: 64..127)
__device__ double g_msep[NMSE_BLOCKS];              // per-block MSE partial sums
__device__ double g_mse_total;                      // fully reduced MSE sum
__device__ double g_row_lp[64];                     // per-row positive-margin term
__device__ double g_row_ln[64];                     // per-row negative-margin sum

__global__ __launch_bounds__(256)
void fused_kernel(const float* __restrict__ o1, const float* __restrict__ z1,
                  const float* __restrict__ o2, const float* __restrict__ z2,
                  const float* __restrict__ i1, const float* __restrict__ i2)
{
    const int tid = threadIdx.x;
    const int b   = blockIdx.x;

    if (b < NCTR_BLOCKS) {
        // ---------- contrastive cross-matrix partial: D slice [b*256, b*256+256) ----------
        // Shared tiles stored k-major: s[k][row], row padded to 68 (68*4 = 272 = 17*16,
        // so &s[k][4*t] stays 16B aligned for LDS.128 on the compute side).
        __shared__ __align__(16) float s1[32][68];
        __shared__ __align__(16) float s2[32][68];

        float acc[4][4];
#pragma unroll
        for (int i = 0; i < 4; ++i)
#pragma unroll
            for (int j = 0; j < 4; ++j) acc[i][j] = 0.0f;

        const int tx = tid & 15;   // n-tile coordinate
        const int ty = tid >> 4;   // m-tile coordinate
        const int c0 = b * 256;

        for (int t = 0; t < 8; ++t) {          // 8 k-tiles of 32
            const int ck = c0 + t * 32;
            __syncthreads();
            // load 64 rows x 32 k each tensor: 512 float4 per tensor, 2 per thread
#pragma unroll
            for (int i = 0; i < 2; ++i) {
                const int idx = tid + i * 256;      // 0..511
                const int r   = idx >> 3;           // row 0..63
                const int kk  = (idx & 7) * 4;      // k within tile
                float4 v1 = *(const float4*)(z1 + r * DZ + ck + kk);
                float4 v2 = *(const float4*)(z2 + r * DZ + ck + kk);
                s1[kk + 0][r] = v1.x; s1[kk + 1][r] = v1.y;
                s1[kk + 2][r] = v1.z; s1[kk + 3][r] = v1.w;
                s2[kk + 0][r] = v2.x; s2[kk + 1][r] = v2.y;
                s2[kk + 2][r] = v2.z; s2[kk + 3][r] = v2.w;
            }
            __syncthreads();
#pragma unroll
            for (int k = 0; k < 32; ++k) {
                const float4 av = *(const float4*)&s1[k][ty * 4];
                const float4 bv = *(const float4*)&s2[k][tx * 4];
                const float a[4] = {av.x, av.y, av.z, av.w};
                const float c[4] = {bv.x, bv.y, bv.z, bv.w};
#pragma unroll
                for (int i = 0; i < 4; ++i)
#pragma unroll
                    for (int j = 0; j < 4; ++j) acc[i][j] += a[i] * c[j];
            }
        }

        float* outp = g_crossp + b * 4096;
#pragma unroll
        for (int i = 0; i < 4; ++i)
#pragma unroll
            for (int j = 0; j < 4; ++j)
                outp[(ty * 4 + i) * 64 + (tx * 4 + j)] = acc[i][j];

        // ---------- COMPLETE sum of squares for row b of z1 (tids 0-127) / z2 (tids 128-255) ----------
        {
            const int g    = tid >> 7;          // 0 -> z1, 1 -> z2
            const int lt   = tid & 127;
            const float* zp = g ? z2 : z1;
            const float4* zr = (const float4*)(zp + b * DZ);
            float s = 0.0f;
#pragma unroll 8
            for (int i = lt; i < 4096; i += 128) {
                const float4 v = zr[i];
                s += v.x * v.x + v.y * v.y + v.z * v.z + v.w * v.w;
            }
#pragma unroll
            for (int o = 16; o; o >>= 1) s += __shfl_down_sync(0xffffffffu, s, o);
            __shared__ float sqred[2][4];
            if ((lt & 31) == 0) sqred[g][lt >> 5] = s;
            __syncthreads();
            if (lt == 0)
                g_sq[g * 64 + b] = sqred[g][0] + sqred[g][1] + sqred[g][2] + sqred[g][3];
        }
    } else {
        // ---------- MSE: fixed 24 iters over a contiguous chunk, unrolled x2 ----------
        const int mb   = b - NCTR_BLOCKS;
        const int base = mb * (MSE_ITERS * 256) + tid;
        const float4* a1 = (const float4*)o1;
        const float4* c1 = (const float4*)i1;
        const float4* a2 = (const float4*)o2;
        const float4* c2 = (const float4*)i2;
        float s0 = 0.0f, s1s = 0.0f;
#pragma unroll
        for (int it = 0; it < MSE_ITERS; it += 2) {
            const int i0 = base + it * 256;
            const int i1i = i0 + 256;
            // 8 independent LDG.128, batched up front
            const float4 xa = __ldcs(a1 + i0);
            const float4 ya = __ldcs(c1 + i0);
            const float4 xb = __ldcs(a2 + i0);
            const float4 yb = __ldcs(c2 + i0);
            const float4 xc = __ldcs(a1 + i1i);
            const float4 yc = __ldcs(c1 + i1i);
            const float4 xd = __ldcs(a2 + i1i);
            const float4 yd = __ldcs(c2 + i1i);
            float dx, dy, dz, dw;
            dx = xa.x - ya.x; dy = xa.y - ya.y; dz = xa.z - ya.z; dw = xa.w - ya.w;
            s0 += dx * dx + dy * dy + dz * dz + dw * dw;
            dx = xb.x - yb.x; dy = xb.y - yb.y; dz = xb.z - yb.z; dw = xb.w - yb.w;
            s0 += dx * dx + dy * dy + dz * dz + dw * dw;
            dx = xc.x - yc.x; dy = xc.y - yc.y; dz = xc.z - yc.z; dw = xc.w - yc.w;
            s1s += dx * dx + dy * dy + dz * dz + dw * dw;
            dx = xd.x - yd.x; dy = xd.y - yd.y; dz = xd.z - yd.z; dw = xd.w - yd.w;
            s1s += dx * dx + dy * dy + dz * dz + dw * dw;
        }
        float sum = s0 + s1s;
        __shared__ float red[8];
#pragma unroll
        for (int off = 16; off; off >>= 1) sum += __shfl_down_sync(0xffffffffu, sum, off);
        if ((tid & 31) == 0) red[tid >> 5] = sum;
        __syncthreads();
        if (tid < 32) {
            float v = (tid < 8) ? red[tid] : 0.0f;
#pragma unroll
            for (int off = 4; off; off >>= 1) v += __shfl_down_sync(0xffffffffu, v, off);
            if (tid == 0) g_msep[mb] = (double)v;
        }
    }
}

// Blocks 0..63: reduce cross row m over the 64 partials + apply margins.
// Block 64: reduce the MSE partials.
__global__ __launch_bounds__(256)
void rowreduce_kernel()
{
    const int tid = threadIdx.x;

    if (blockIdx.x == 64) {
        __shared__ double mred[8];
        double msum = 0.0;
#pragma unroll
        for (int i = tid; i < NMSE_BLOCKS; i += 256) msum += g_msep[i];
#pragma unroll
        for (int o = 16; o; o >>= 1) msum += __shfl_down_sync(0xffffffffu, msum, o);
        if ((tid & 31) == 0) mred[tid >> 5] = msum;
        __syncthreads();
        if (tid == 0) {
            double t = 0.0;
#pragma unroll
            for (int i = 0; i < 8; ++i) t += mred[i];
            g_mse_total = t;
        }
        return;
    }

    const int m = blockIdx.x;
    const int n = tid & 63;       // output column
    const int q = tid >> 6;       // partial group 0..3 (16 partials each)

    float s = 0.0f;
#pragma unroll
    for (int j = 0; j < 16; ++j)
        s += g_crossp[(q * 16 + j) * 4096 + m * 64 + n];

    __shared__ float sm[4][64];
    __shared__ double dred[2];
    sm[q][n] = s;
    __syncthreads();

    if (tid < 64) {
        const float cr = sm[0][tid] + sm[1][tid] + sm[2][tid] + sm[3][tid];
        const double d = ((double)g_sq[m] + (double)g_sq[64 + tid] - 2.0 * (double)cr)
                         * (1.0 / (double)DZ);
        double lp = 0.0, ln = 0.0;
        if (m == tid) {
            if (d > 0.01) lp = d - 0.01;
        } else if (d < 0.4) {
            ln = 0.4 - d;
        }
#pragma unroll
        for (int o = 16; o; o >>= 1) {
            lp += __shfl_down_sync(0xffffffffu, lp, o);
            ln += __shfl_down_sync(0xffffffffu, ln, o);
        }
        if ((tid & 31) == 0) dred[tid >> 5] = ln + lp;   // lp folded in (only one warp has it)
        __syncthreads();
        if (tid == 0) {
            // separate lp exactly: recompute diagonal term directly (cheap, deterministic)
            const double dd = ((double)g_sq[m] + (double)g_sq[64 + m]
                               - 2.0 * (double)(sm[0][m] + sm[1][m] + sm[2][m] + sm[3][m]))
                              * (1.0 / (double)DZ);
            const double lpv = (dd > 0.01) ? (dd - 0.01) : 0.0;
            g_row_lp[m] = lpv;
            g_row_ln[m] = dred[0] + dred[1] - lpv;
        }
    }
}

__device__ __forceinline__ double warp_red_d(double v)
{
#pragma unroll
    for (int o = 16; o; o >>= 1) v += __shfl_down_sync(0xffffffffu, v, o);
    return v;
}

__global__ __launch_bounds__(64)
void finalize_kernel(float* __restrict__ out)
{
    const int tid = threadIdx.x;
    __shared__ double sred[2][2];

    const double lp = g_row_lp[tid];
    const double ln = g_row_ln[tid];
    const double r1 = warp_red_d(lp);
    const double r2 = warp_red_d(ln);
    if ((tid & 31) == 0) { sred[0][tid >> 5] = r1; sred[1][tid >> 5] = r2; }
    __syncthreads();
    if (tid == 0) {
        const double recon = g_mse_total / (double)NEL;            // mean1 + mean2 combined
        const double lossP = 1.5 * ((sred[0][0] + sred[0][1]) / (double)BZ);
        const double lossN = 0.5 * ((sred[1][0] + sred[1][1]) / (double)(BZ * (BZ - 1)));
        out[0] = (float)(recon + lossP + lossN);
    }
}

extern "C" void kernel_launch(void* const* d_in, const int* in_sizes, int n_in,
                              void* d_out, int out_size)
{
    const float* o1 = (const float*)d_in[0];
    const float* z1 = (const float*)d_in[1];
    const float* o2 = (const float*)d_in[2];
    const float* z2 = (const float*)d_in[3];
    const float* i1 = (const float*)d_in[4];
    const float* i2 = (const float*)d_in[5];

    fused_kernel<<<TOTAL_BLOCKS, 256>>>(o1, z1, o2, z2, i1, i2);
    rowreduce_kernel<<<65, 256>>>();
    finalize_kernel<<<1, 64>>>((float*)d_out);
}